// round 15
// baseline (speedup 1.0000x reference)
#include <cuda_runtime.h>
#include <cuda_fp16.h>
#include <cstdint>

// ---------------- problem constants ----------------
#define BS   2
#define NQ   21760
#define EMBED 256
#define NH   8
#define HD   32
#define MROWS (BS * NQ)   // 43520 = 340 * 128

__device__ __constant__ int c_dim[4]   = {128, 64, 32, 16};
__device__ __constant__ int c_start[4] = {0, 16384, 20480, 21504};

// ---------------- scratch ----------------
__device__ __align__(256) __half g_qh[MROWS * EMBED];
__device__ __align__(256) __half g_valh[MROWS * EMBED];
__device__ __align__(256) float  g_offaw[MROWS * 384];
__device__ __align__(256) __half g_vhm[MROWS * EMBED];   // [b][h][tok][32]
__device__ __align__(256) __half g_samph[MROWS * EMBED];
__device__ __align__(256) __half g_wtcat[384 * EMBED];
__device__ __align__(256) __half g_wtv[EMBED * EMBED];
__device__ __align__(256) __half g_wtout[EMBED * EMBED];
__device__ __align__(256) float  g_bcat[384];

// ---------------- helpers ----------------
__device__ __forceinline__ uint32_t smem_u32(const void* p) {
    uint32_t a;
    asm("{ .reg .u64 t; cvta.to.shared.u64 t, %1; cvt.u32.u64 %0, t; }"
        : "=r"(a) : "l"(p));
    return a;
}

#define LDSM4(r0, r1, r2, r3, addr)                                           \
    asm volatile("ldmatrix.sync.aligned.m8n8.x4.shared.b16 {%0,%1,%2,%3}, [%4];" \
                 : "=r"(r0), "=r"(r1), "=r"(r2), "=r"(r3) : "r"(addr))

#define CP16(dst, src)                                                        \
    asm volatile("cp.async.cg.shared.global [%0], [%1], 16;"                  \
                 :: "r"(dst), "l"(src) : "memory")
#define CP_COMMIT asm volatile("cp.async.commit_group;" ::: "memory")
#define CP_WAIT1  asm volatile("cp.async.wait_group 1;" ::: "memory")

__device__ __forceinline__ void mma_f16(float* d, const uint32_t* a,
                                        uint32_t b0, uint32_t b1) {
    asm volatile(
        "mma.sync.aligned.m16n8k16.row.col.f32.f16.f16.f32 "
        "{%0,%1,%2,%3}, {%4,%5,%6,%7}, {%8,%9}, {%0,%1,%2,%3};"
        : "+f"(d[0]), "+f"(d[1]), "+f"(d[2]), "+f"(d[3])
        : "r"(a[0]), "r"(a[1]), "r"(a[2]), "r"(a[3]), "r"(b0), "r"(b1));
}

// ---------------- prep: f2h(query,value) + weight transpose + bias, 1 launch
#define F2H_BLKS (MROWS * 256 / 2048)   // 5440 per tensor
__global__ void prep_all(const float* __restrict__ q, const float* __restrict__ v,
                         __half* __restrict__ qo, __half* __restrict__ vo,
                         const float* __restrict__ W_off,
                         const float* __restrict__ W_attn,
                         const float* __restrict__ W_v,
                         const float* __restrict__ W_out,
                         const float* __restrict__ b_off,
                         const float* __restrict__ b_attn,
                         __half* __restrict__ wtcat,
                         __half* __restrict__ wtv,
                         __half* __restrict__ wtout,
                         float* __restrict__ bcat)
{
    const int g = blockIdx.x;
    if (g < 2 * F2H_BLKS) {
        const bool second = g >= F2H_BLKS;
        const float*  in  = second ? v : q;
        __half*       out = second ? vo : qo;
        const size_t i = ((size_t)(second ? g - F2H_BLKS : g) * 256 +
                          threadIdx.x) * 8;
        const float4 x0 = *(const float4*)(in + i);
        const float4 x1 = *(const float4*)(in + i + 4);
        __half2 h0 = __floats2half2_rn(x0.x, x0.y);
        __half2 h1 = __floats2half2_rn(x0.z, x0.w);
        __half2 h2 = __floats2half2_rn(x1.x, x1.y);
        __half2 h3 = __floats2half2_rn(x1.z, x1.w);
        *(uint4*)(out + i) = make_uint4(*(uint32_t*)&h0, *(uint32_t*)&h1,
                                        *(uint32_t*)&h2, *(uint32_t*)&h3);
        return;
    }
    __shared__ float t[32][33];
    int bid = g - 2 * F2H_BLKS;
    const int tx = threadIdx.x & 31;
    const int ty = threadIdx.x >> 5;
    if (bid == 224) {
        const int i = threadIdx.x;
        bcat[i] = b_off[i];
        if (i < 128) bcat[256 + i] = b_attn[i];
        return;
    }
    const float* in;
    __half* outb;
    int cx, ry, C;
    if (bid < 64)        { in = W_off;  outb = wtcat;         cx = bid & 7; ry = bid >> 3; C = 256; }
    else if (bid < 96)   { bid -= 64;  in = W_attn; outb = wtcat + 65536; cx = bid & 3; ry = bid >> 2; C = 128; }
    else if (bid < 160)  { bid -= 96;  in = W_v;    outb = wtv;   cx = bid & 7; ry = bid >> 3; C = 256; }
    else                 { bid -= 160; in = W_out;  outb = wtout; cx = bid & 7; ry = bid >> 3; C = 256; }
    const int c0 = cx * 32, r0 = ry * 32;
    for (int i = ty; i < 32; i += 8)
        t[i][tx] = in[(size_t)(r0 + i) * C + c0 + tx];
    __syncthreads();
    for (int i = ty; i < 32; i += 8)
        outb[(size_t)(c0 + i) * 256 + r0 + tx] = __float2half_rn(t[tx][i]);
}

// ---------------- fp16 tensor-core GEMM body ----------------
// 512 threads, 16 warps as 4(m) x 4(n); warp tile 32x32 -> acc = 32 regs.
// Same 128x128 CTA tile, BK=64, 3-stage cp.async, 1 barrier per chunk,
// same canonical SW128 swizzle (row*128 + (col ^ ((row&7)*16))).
__device__ __forceinline__ void gemm_body(
    const __half* __restrict__ A, const __half* __restrict__ Bt,
    const float* __restrict__ bias, void* __restrict__ C,
    int Nstr, int outmode, int m0, int n0, uint32_t stBase)
{
    const int tid  = threadIdx.x;
    const int lane = tid & 31;
    const int wid  = tid >> 5;
    const int wm   = wid & 3;        // 32-row group
    const int wn   = wid >> 2;       // 32-col group
    const int t4   = lane >> 2;
    const int tq   = lane & 3;

    // cp.async staging: 1024 segs/operand-tile; thread -> 2 segs per operand
    const int rbase = tid >> 3;      // 0..63
    const int seg   = tid & 7;
    const uint32_t segx = (uint32_t)((seg * 16) ^ ((rbase & 7) * 16));
    const __half* srcA = A + (size_t)(m0 + rbase) * 256 + seg * 8;
    const __half* srcB = Bt + (size_t)(n0 + rbase) * 256 + seg * 8;

    // ldmatrix addressing
    const int midx  = lane >> 3;
    const int khalf = midx >> 1;
    const int rsel  = ((midx & 1) << 3) + (lane & 7);
    const uint32_t key = (uint32_t)((lane & 7) * 16);
    uint32_t colx[4];
#pragma unroll
    for (int ks = 0; ks < 4; ks++)
        colx[ks] = (uint32_t)((2 * ks + khalf) * 16) ^ key;
    const uint32_t aRow = (uint32_t)((wm * 32 + rsel) * 128);
    const uint32_t bRow = (uint32_t)((wn * 32 + rsel) * 128) + 16384;

    float acc[2][4][4];
#pragma unroll
    for (int i = 0; i < 2; i++)
#pragma unroll
        for (int j = 0; j < 4; j++)
#pragma unroll
            for (int k = 0; k < 4; k++) acc[i][j][k] = 0.f;

    // prologue: chunks 0,1 into stages 0,1
#pragma unroll
    for (int s = 0; s < 2; s++) {
        const uint32_t st = stBase + s * 32768;
#pragma unroll
        for (int i = 0; i < 2; i++) {
            const uint32_t d = (uint32_t)((rbase + i * 64) * 128) + segx;
            CP16(st + d,         srcA + s * 64 + i * 64 * 256);
            CP16(st + 16384 + d, srcB + s * 64 + i * 64 * 256);
        }
        CP_COMMIT;
    }

#pragma unroll
    for (int c = 0; c < 4; c++) {
        CP_WAIT1;
        __syncthreads();

        if (c + 2 < 4) {
            const uint32_t st = stBase + ((c + 2) % 3) * 32768;
#pragma unroll
            for (int i = 0; i < 2; i++) {
                const uint32_t d = (uint32_t)((rbase + i * 64) * 128) + segx;
                CP16(st + d,         srcA + (c + 2) * 64 + i * 64 * 256);
                CP16(st + 16384 + d, srcB + (c + 2) * 64 + i * 64 * 256);
            }
        }
        CP_COMMIT;

        const uint32_t bufA = stBase + (c % 3) * 32768;
#pragma unroll
        for (int ks = 0; ks < 4; ks++) {
            uint32_t a[2][4], b[2][4];
#pragma unroll
            for (int mt = 0; mt < 2; mt++)
                LDSM4(a[mt][0], a[mt][1], a[mt][2], a[mt][3],
                      bufA + aRow + mt * 2048 + colx[ks]);
#pragma unroll
            for (int np = 0; np < 2; np++)
                LDSM4(b[np][0], b[np][1], b[np][2], b[np][3],
                      bufA + bRow + np * 2048 + colx[ks]);
#pragma unroll
            for (int mt = 0; mt < 2; mt++)
#pragma unroll
                for (int nt = 0; nt < 4; nt++)
                    mma_f16(acc[mt][nt], a[mt], b[nt >> 1][nt & 1],
                            b[nt >> 1][(nt & 1) + 2]);
        }
    }

    // epilogue
#pragma unroll
    for (int nt = 0; nt < 4; nt++) {
        const int col = n0 + wn * 32 + nt * 8 + tq * 2;
        const float2 bb = *(const float2*)(bias + col);
#pragma unroll
        for (int mt = 0; mt < 2; mt++) {
            const int row = m0 + wm * 32 + mt * 16 + t4;
            if (outmode == 0) {
                float2 o0 = {acc[mt][nt][0] + bb.x, acc[mt][nt][1] + bb.y};
                float2 o1 = {acc[mt][nt][2] + bb.x, acc[mt][nt][3] + bb.y};
                *(float2*)((float*)C + (size_t)row * Nstr + col) = o0;
                *(float2*)((float*)C + (size_t)(row + 8) * Nstr + col) = o1;
            } else {
                const int h = col >> 5, ch = col & 31;
                __half2 h0 = __floats2half2_rn(acc[mt][nt][0] + bb.x,
                                               acc[mt][nt][1] + bb.y);
                __half2 h1 = __floats2half2_rn(acc[mt][nt][2] + bb.x,
                                               acc[mt][nt][3] + bb.y);
                const int b0i = row / NQ,       tok0 = row - b0i * NQ;
                const int b1i = (row + 8) / NQ, tok1 = (row + 8) - b1i * NQ;
                __half* V = (__half*)C;
                *(uint32_t*)(V + (((size_t)b0i * 8 + h) * NQ + tok0) * 32 + ch) =
                    *(uint32_t*)&h0;
                *(uint32_t*)(V + (((size_t)b1i * 8 + h) * NQ + tok1) * 32 + ch) =
                    *(uint32_t*)&h1;
            }
        }
    }
}

__global__ __launch_bounds__(512, 2) void hgemm_dual(
    const __half* __restrict__ qh, const __half* __restrict__ wtcat,
    const float* __restrict__ bcat, float* __restrict__ offaw,
    const __half* __restrict__ valh, const __half* __restrict__ wtv,
    const float* __restrict__ bv, __half* __restrict__ vhm)
{
    extern __shared__ __align__(1024) uint8_t smem[];
    const uint32_t st = smem_u32(smem);
    const int m0 = blockIdx.y * 128;
    if (blockIdx.x < 3)
        gemm_body(qh, wtcat, bcat, offaw, 384, 0, m0, blockIdx.x * 128, st);
    else
        gemm_body(valh, wtv, bv, vhm, 256, 1, m0, (blockIdx.x - 3) * 128, st);
}

__global__ __launch_bounds__(512, 2) void hgemm_single(
    const __half* __restrict__ A, const __half* __restrict__ Bt,
    const float* __restrict__ bias, float* __restrict__ C)
{
    extern __shared__ __align__(1024) uint8_t smem[];
    gemm_body(A, Bt, bias, C, 256, 0, blockIdx.y * 128, blockIdx.x * 128,
              smem_u32(smem));
}

// ---------------- fused softmax + deformable sampling (R9/R12 winner) -------
__global__ __launch_bounds__(256) void deform_sample6(
    const float* __restrict__ ref, const float* __restrict__ offaw,
    const __half* __restrict__ vhm, __half* __restrict__ samph)
{
    __shared__ uint2 sm[8][128][4];   // [warp][h*16+s][corner] = (tok, w)

    const int w    = threadIdx.x >> 5;
    const int lane = threadIdx.x & 31;
    const int bq   = blockIdx.x * 8 + w;
    const int b    = bq / NQ;

    {   // ---- phase 1 ----
        const int h = lane >> 2;
        const int j = lane & 3;
        const float* aw = offaw + (size_t)bq * 384 + 256;
        float lg[4];
#pragma unroll
        for (int r = 0; r < 4; r++) lg[r] = aw[h * 16 + r * 4 + j];
        float mx = fmaxf(fmaxf(lg[0], lg[1]), fmaxf(lg[2], lg[3]));
        mx = fmaxf(mx, __shfl_xor_sync(0xffffffffu, mx, 1));
        mx = fmaxf(mx, __shfl_xor_sync(0xffffffffu, mx, 2));
        float e[4], sum = 0.f;
#pragma unroll
        for (int r = 0; r < 4; r++) { e[r] = __expf(lg[r] - mx); sum += e[r]; }
        sum += __shfl_xor_sync(0xffffffffu, sum, 1);
        sum += __shfl_xor_sync(0xffffffffu, sum, 2);
        const float inv = 1.f / sum;

        const float2* offp = (const float2*)(offaw + (size_t)bq * 384);
        const float2* refp = (const float2*)(ref + (size_t)bq * 8);
#pragma unroll
        for (int r = 0; r < 4; r++) {
            const int s = r * 4 + j;
            const int W = c_dim[r];
            const int st = c_start[r];
            const float2 o2 = offp[h * 16 + s];
            const float2 r2 = refp[r];
            const float x = fmaf(r2.x, (float)W, o2.x) - 0.5f;
            const float y = fmaf(r2.y, (float)W, o2.y) - 0.5f;
            const float xf = floorf(x), yf = floorf(y);
            const int x0 = (int)xf, y0 = (int)yf;
            const float fx = x - xf, fy = y - yf;
            const float mx0 = ((unsigned)x0 < (unsigned)W) ? 1.f : 0.f;
            const float mx1 = ((unsigned)(x0 + 1) < (unsigned)W) ? 1.f : 0.f;
            const float my0 = ((unsigned)y0 < (unsigned)W) ? 1.f : 0.f;
            const float my1 = ((unsigned)(y0 + 1) < (unsigned)W) ? 1.f : 0.f;
            const float ww = e[r] * inv;
            const float wx0 = (1.f - fx) * mx0, wx1 = fx * mx1;
            const float wy0 = (1.f - fy) * my0, wy1 = fy * my1;
            const int xc0 = min(max(x0, 0), W - 1);
            const int xc1 = min(max(x0 + 1, 0), W - 1);
            const int yc0 = min(max(y0, 0), W - 1);
            const int yc1 = min(max(y0 + 1, 0), W - 1);
            const int t00 = st + yc0 * W + xc0;
            const int t01 = st + yc0 * W + xc1;
            const int t10 = st + yc1 * W + xc0;
            const int t11 = st + yc1 * W + xc1;
            const float w00 = ww * wy0 * wx0;
            const float w01 = ww * wy0 * wx1;
            const float w10 = ww * wy1 * wx0;
            const float w11 = ww * wy1 * wx1;
            *(uint4*)&sm[w][h * 16 + s][0] =
                make_uint4((uint32_t)t00, __float_as_uint(w00),
                           (uint32_t)t01, __float_as_uint(w01));
            *(uint4*)&sm[w][h * 16 + s][2] =
                make_uint4((uint32_t)t10, __float_as_uint(w10),
                           (uint32_t)t11, __float_as_uint(w11));
        }
    }
    __syncwarp();

    // ---- phase 2 ----
    const int item_hi = lane >> 3;
    const int sub     = lane & 7;
    const int c2      = sub >> 2;
    const int chsl    = sub & 3;

#pragma unroll 1
    for (int h = 0; h < 8; h++) {
        const __half* vbh = vhm + ((size_t)(b * 8 + h)) * (NQ * 32);
        float av[8];
#pragma unroll
        for (int k = 0; k < 8; k++) av[k] = 0.f;

#pragma unroll
        for (int ldg = 0; ldg < 8; ldg++) {
            const int it  = ldg * 4 + item_hi;
            const int t   = it >> 1;
            const int i4  = (it & 1) * 2 + c2;
            const uint2 tw = sm[w][h * 16 + t][i4];
            const int tok  = (int)tw.x;
            const float wt = __uint_as_float(tw.y);
            const uint4 raw = *(const uint4*)(vbh + (size_t)tok * 32 + chsl * 8);
            const float2 f0 = __half22float2(*(const __half2*)&raw.x);
            const float2 f1 = __half22float2(*(const __half2*)&raw.y);
            const float2 f2 = __half22float2(*(const __half2*)&raw.z);
            const float2 f3 = __half22float2(*(const __half2*)&raw.w);
            av[0] = fmaf(wt, f0.x, av[0]);
            av[1] = fmaf(wt, f0.y, av[1]);
            av[2] = fmaf(wt, f1.x, av[2]);
            av[3] = fmaf(wt, f1.y, av[3]);
            av[4] = fmaf(wt, f2.x, av[4]);
            av[5] = fmaf(wt, f2.y, av[5]);
            av[6] = fmaf(wt, f3.x, av[6]);
            av[7] = fmaf(wt, f3.y, av[7]);
        }

#pragma unroll
        for (int o = 4; o <= 16; o <<= 1)
#pragma unroll
            for (int k = 0; k < 8; k++)
                av[k] += __shfl_xor_sync(0xffffffffu, av[k], o);

        if (lane < 4) {
            __half2 h0 = __floats2half2_rn(av[0], av[1]);
            __half2 h1 = __floats2half2_rn(av[2], av[3]);
            __half2 h2 = __floats2half2_rn(av[4], av[5]);
            __half2 h3 = __floats2half2_rn(av[6], av[7]);
            uint4 u = make_uint4(*(uint32_t*)&h0, *(uint32_t*)&h1,
                                 *(uint32_t*)&h2, *(uint32_t*)&h3);
            *(uint4*)(samph + (size_t)bq * 256 + h * 32 + lane * 8) = u;
        }
    }
}

// ---------------- launch ----------------
extern "C" void kernel_launch(void* const* d_in, const int* in_sizes, int n_in,
                              void* d_out, int out_size)
{
    const float* query  = (const float*)d_in[0];
    const float* refpts = (const float*)d_in[1];
    const float* value  = (const float*)d_in[2];
    const float* W_off  = (const float*)d_in[3];
    const float* b_off  = (const float*)d_in[4];
    const float* W_attn = (const float*)d_in[5];
    const float* b_attn = (const float*)d_in[6];
    const float* W_v    = (const float*)d_in[7];
    const float* b_v    = (const float*)d_in[8];
    const float* W_out  = (const float*)d_in[9];
    const float* b_out  = (const float*)d_in[10];
    float* out = (float*)d_out;

    float *offaw_s, *bcat;
    __half *qh_s, *valh_s, *vhm_s, *samph_s, *wtcat, *wtv, *wtout;
    cudaGetSymbolAddress((void**)&qh_s,    g_qh);
    cudaGetSymbolAddress((void**)&valh_s,  g_valh);
    cudaGetSymbolAddress((void**)&offaw_s, g_offaw);
    cudaGetSymbolAddress((void**)&vhm_s,   g_vhm);
    cudaGetSymbolAddress((void**)&samph_s, g_samph);
    cudaGetSymbolAddress((void**)&wtcat,   g_wtcat);
    cudaGetSymbolAddress((void**)&wtv,     g_wtv);
    cudaGetSymbolAddress((void**)&wtout,   g_wtout);
    cudaGetSymbolAddress((void**)&bcat,    g_bcat);

    static bool attr_done = false;
    if (!attr_done) {
        cudaFuncSetAttribute(hgemm_dual,
                             cudaFuncAttributeMaxDynamicSharedMemorySize, 98304);
        cudaFuncSetAttribute(hgemm_single,
                             cudaFuncAttributeMaxDynamicSharedMemorySize, 98304);
        attr_done = true;
    }

    prep_all<<<2 * F2H_BLKS + 225, 256>>>(query, value, qh_s, valh_s,
                                          W_off, W_attn, W_v, W_out,
                                          b_off, b_attn,
                                          wtcat, wtv, wtout, bcat);

    const int GM = MROWS / 128;   // 340
    hgemm_dual<<<dim3(5, GM), 512, 98304>>>(qh_s, wtcat, bcat, offaw_s,
                                            valh_s, wtv, b_v, vhm_s);

    deform_sample6<<<MROWS / 8, 256>>>(refpts, offaw_s, vhm_s, samph_s);

    hgemm_single<<<dim3(2, GM), 512, 98304>>>(samph_s, wtout, b_out, out);
}

// round 16
// speedup vs baseline: 1.0441x; 1.0441x over previous
#include <cuda_runtime.h>
#include <cuda_fp16.h>
#include <cstdint>

// ---------------- problem constants ----------------
#define BS   2
#define NQ   21760
#define EMBED 256
#define NH   8
#define HD   32
#define MROWS (BS * NQ)   // 43520 = 340 * 128

__device__ __constant__ int c_dim[4]   = {128, 64, 32, 16};
__device__ __constant__ int c_start[4] = {0, 16384, 20480, 21504};

// ---------------- scratch ----------------
__device__ __align__(256) __half g_qh[MROWS * EMBED];
__device__ __align__(256) __half g_valh[MROWS * EMBED];
__device__ __align__(256) float  g_offaw[MROWS * 384];
__device__ __align__(256) __half g_vhm[MROWS * EMBED];   // [b][h][tok][32]
__device__ __align__(256) __half g_samph[MROWS * EMBED];
__device__ __align__(256) __half g_wtcat[384 * EMBED];
__device__ __align__(256) __half g_wtv[EMBED * EMBED];
__device__ __align__(256) __half g_wtout[EMBED * EMBED];
__device__ __align__(256) float  g_bcat[384];

// ---------------- helpers ----------------
__device__ __forceinline__ uint32_t smem_u32(const void* p) {
    uint32_t a;
    asm("{ .reg .u64 t; cvta.to.shared.u64 t, %1; cvt.u32.u64 %0, t; }"
        : "=r"(a) : "l"(p));
    return a;
}

#define LDSM4(r0, r1, r2, r3, addr)                                           \
    asm volatile("ldmatrix.sync.aligned.m8n8.x4.shared.b16 {%0,%1,%2,%3}, [%4];" \
                 : "=r"(r0), "=r"(r1), "=r"(r2), "=r"(r3) : "r"(addr))

#define CP16(dst, src)                                                        \
    asm volatile("cp.async.cg.shared.global [%0], [%1], 16;"                  \
                 :: "r"(dst), "l"(src) : "memory")
#define CP_COMMIT asm volatile("cp.async.commit_group;" ::: "memory")
#define CP_WAIT1  asm volatile("cp.async.wait_group 1;" ::: "memory")

__device__ __forceinline__ void mma_f16(float* d, const uint32_t* a,
                                        uint32_t b0, uint32_t b1) {
    asm volatile(
        "mma.sync.aligned.m16n8k16.row.col.f32.f16.f16.f32 "
        "{%0,%1,%2,%3}, {%4,%5,%6,%7}, {%8,%9}, {%0,%1,%2,%3};"
        : "+f"(d[0]), "+f"(d[1]), "+f"(d[2]), "+f"(d[3])
        : "r"(a[0]), "r"(a[1]), "r"(a[2]), "r"(a[3]), "r"(b0), "r"(b1));
}

// ---------------- prep: f2h(query,value) + weight transpose + bias, 1 launch
#define F2H_BLKS (MROWS * 256 / 2048)   // 5440 per tensor
__global__ void prep_all(const float* __restrict__ q, const float* __restrict__ v,
                         __half* __restrict__ qo, __half* __restrict__ vo,
                         const float* __restrict__ W_off,
                         const float* __restrict__ W_attn,
                         const float* __restrict__ W_v,
                         const float* __restrict__ W_out,
                         const float* __restrict__ b_off,
                         const float* __restrict__ b_attn,
                         __half* __restrict__ wtcat,
                         __half* __restrict__ wtv,
                         __half* __restrict__ wtout,
                         float* __restrict__ bcat)
{
    const int g = blockIdx.x;
    if (g < 2 * F2H_BLKS) {
        const bool second = g >= F2H_BLKS;
        const float*  in  = second ? v : q;
        __half*       out = second ? vo : qo;
        const size_t i = ((size_t)(second ? g - F2H_BLKS : g) * 256 +
                          threadIdx.x) * 8;
        const float4 x0 = *(const float4*)(in + i);
        const float4 x1 = *(const float4*)(in + i + 4);
        __half2 h0 = __floats2half2_rn(x0.x, x0.y);
        __half2 h1 = __floats2half2_rn(x0.z, x0.w);
        __half2 h2 = __floats2half2_rn(x1.x, x1.y);
        __half2 h3 = __floats2half2_rn(x1.z, x1.w);
        *(uint4*)(out + i) = make_uint4(*(uint32_t*)&h0, *(uint32_t*)&h1,
                                        *(uint32_t*)&h2, *(uint32_t*)&h3);
        return;
    }
    __shared__ float t[32][33];
    int bid = g - 2 * F2H_BLKS;
    const int tx = threadIdx.x & 31;
    const int ty = threadIdx.x >> 5;
    if (bid == 224) {
        const int i = threadIdx.x;
        bcat[i] = b_off[i];
        if (i < 128) bcat[256 + i] = b_attn[i];
        return;
    }
    const float* in;
    __half* outb;
    int cx, ry, C;
    if (bid < 64)        { in = W_off;  outb = wtcat;         cx = bid & 7; ry = bid >> 3; C = 256; }
    else if (bid < 96)   { bid -= 64;  in = W_attn; outb = wtcat + 65536; cx = bid & 3; ry = bid >> 2; C = 128; }
    else if (bid < 160)  { bid -= 96;  in = W_v;    outb = wtv;   cx = bid & 7; ry = bid >> 3; C = 256; }
    else                 { bid -= 160; in = W_out;  outb = wtout; cx = bid & 7; ry = bid >> 3; C = 256; }
    const int c0 = cx * 32, r0 = ry * 32;
    for (int i = ty; i < 32; i += 8)
        t[i][tx] = in[(size_t)(r0 + i) * C + c0 + tx];
    __syncthreads();
    for (int i = ty; i < 32; i += 8)
        outb[(size_t)(c0 + i) * 256 + r0 + tx] = __float2half_rn(t[tx][i]);
}

// ---------------- fp16 tensor-core GEMM body (R14 verified config) ---------
// 256 threads, 8 warps (2m x 4n), warp tile 64x32, BK=64, 3-stage cp.async.
__device__ __forceinline__ void gemm_body(
    const __half* __restrict__ A, const __half* __restrict__ Bt,
    const float* __restrict__ bias, void* __restrict__ C,
    int Nstr, int outmode, int m0, int n0, uint32_t stBase)
{
    const int tid  = threadIdx.x;
    const int lane = tid & 31;
    const int wid  = tid >> 5;
    const int wm   = wid & 1;
    const int wn   = wid >> 1;
    const int t4   = lane >> 2;
    const int tq   = lane & 3;

    const int rbase = tid >> 3;
    const int seg   = tid & 7;
    const uint32_t segx = (uint32_t)((seg * 16) ^ ((rbase & 7) * 16));
    const __half* srcA = A + (size_t)(m0 + rbase) * 256 + seg * 8;
    const __half* srcB = Bt + (size_t)(n0 + rbase) * 256 + seg * 8;

    const int midx  = lane >> 3;
    const int khalf = midx >> 1;
    const int rsel  = ((midx & 1) << 3) + (lane & 7);
    const uint32_t key = (uint32_t)((lane & 7) * 16);
    uint32_t colx[4];
#pragma unroll
    for (int ks = 0; ks < 4; ks++)
        colx[ks] = (uint32_t)((2 * ks + khalf) * 16) ^ key;
    const uint32_t aRow = (uint32_t)((wm * 64 + rsel) * 128);
    const uint32_t bRow = (uint32_t)((wn * 32 + rsel) * 128) + 16384;

    float acc[4][4][4];
#pragma unroll
    for (int i = 0; i < 4; i++)
#pragma unroll
        for (int j = 0; j < 4; j++)
#pragma unroll
            for (int k = 0; k < 4; k++) acc[i][j][k] = 0.f;

#pragma unroll
    for (int s = 0; s < 2; s++) {
        const uint32_t st = stBase + s * 32768;
#pragma unroll
        for (int i = 0; i < 4; i++) {
            const uint32_t d = (uint32_t)((rbase + i * 32) * 128) + segx;
            CP16(st + d,         srcA + s * 64 + i * 32 * 256);
            CP16(st + 16384 + d, srcB + s * 64 + i * 32 * 256);
        }
        CP_COMMIT;
    }

#pragma unroll
    for (int c = 0; c < 4; c++) {
        CP_WAIT1;
        __syncthreads();

        if (c + 2 < 4) {
            const uint32_t st = stBase + ((c + 2) % 3) * 32768;
#pragma unroll
            for (int i = 0; i < 4; i++) {
                const uint32_t d = (uint32_t)((rbase + i * 32) * 128) + segx;
                CP16(st + d,         srcA + (c + 2) * 64 + i * 32 * 256);
                CP16(st + 16384 + d, srcB + (c + 2) * 64 + i * 32 * 256);
            }
        }
        CP_COMMIT;

        const uint32_t bufA = stBase + (c % 3) * 32768;
#pragma unroll
        for (int ks = 0; ks < 4; ks++) {
            uint32_t a[4][4], b[2][4];
#pragma unroll
            for (int mt = 0; mt < 4; mt++)
                LDSM4(a[mt][0], a[mt][1], a[mt][2], a[mt][3],
                      bufA + aRow + mt * 2048 + colx[ks]);
#pragma unroll
            for (int np = 0; np < 2; np++)
                LDSM4(b[np][0], b[np][1], b[np][2], b[np][3],
                      bufA + bRow + np * 2048 + colx[ks]);
#pragma unroll
            for (int mt = 0; mt < 4; mt++)
#pragma unroll
                for (int nt = 0; nt < 4; nt++)
                    mma_f16(acc[mt][nt], a[mt], b[nt >> 1][nt & 1],
                            b[nt >> 1][(nt & 1) + 2]);
        }
    }

#pragma unroll
    for (int nt = 0; nt < 4; nt++) {
        const int col = n0 + wn * 32 + nt * 8 + tq * 2;
        const float2 bb = *(const float2*)(bias + col);
#pragma unroll
        for (int mt = 0; mt < 4; mt++) {
            const int row = m0 + wm * 64 + mt * 16 + t4;
            if (outmode == 0) {
                float2 o0 = {acc[mt][nt][0] + bb.x, acc[mt][nt][1] + bb.y};
                float2 o1 = {acc[mt][nt][2] + bb.x, acc[mt][nt][3] + bb.y};
                *(float2*)((float*)C + (size_t)row * Nstr + col) = o0;
                *(float2*)((float*)C + (size_t)(row + 8) * Nstr + col) = o1;
            } else {
                const int h = col >> 5, ch = col & 31;
                __half2 h0 = __floats2half2_rn(acc[mt][nt][0] + bb.x,
                                               acc[mt][nt][1] + bb.y);
                __half2 h1 = __floats2half2_rn(acc[mt][nt][2] + bb.x,
                                               acc[mt][nt][3] + bb.y);
                const int b0i = row / NQ,       tok0 = row - b0i * NQ;
                const int b1i = (row + 8) / NQ, tok1 = (row + 8) - b1i * NQ;
                __half* V = (__half*)C;
                *(uint32_t*)(V + (((size_t)b0i * 8 + h) * NQ + tok0) * 32 + ch) =
                    *(uint32_t*)&h0;
                *(uint32_t*)(V + (((size_t)b1i * 8 + h) * NQ + tok1) * 32 + ch) =
                    *(uint32_t*)&h1;
            }
        }
    }
}

__global__ __launch_bounds__(256, 2) void hgemm_dual(
    const __half* __restrict__ qh, const __half* __restrict__ wtcat,
    const float* __restrict__ bcat, float* __restrict__ offaw,
    const __half* __restrict__ valh, const __half* __restrict__ wtv,
    const float* __restrict__ bv, __half* __restrict__ vhm)
{
    extern __shared__ __align__(1024) uint8_t smem[];
    const uint32_t st = smem_u32(smem);
    const int m0 = blockIdx.y * 128;
    if (blockIdx.x < 3)
        gemm_body(qh, wtcat, bcat, offaw, 384, 0, m0, blockIdx.x * 128, st);
    else
        gemm_body(valh, wtv, bv, vhm, 256, 1, m0, (blockIdx.x - 3) * 128, st);
}

__global__ __launch_bounds__(256, 2) void hgemm_single(
    const __half* __restrict__ A, const __half* __restrict__ Bt,
    const float* __restrict__ bias, float* __restrict__ C)
{
    extern __shared__ __align__(1024) uint8_t smem[];
    gemm_body(A, Bt, bias, C, 256, 0, blockIdx.y * 128, blockIdx.x * 128,
              smem_u32(smem));
}

// ---------------- fused softmax + deformable sampling -----------------------
// R9/R12 winner body, unchanged per-warp. ONLY change: 512 threads (16 warps)
// per CTA with the corner table in 64KB DYNAMIC smem -> 3 CTAs x 16 warps =
// 48 warps/SM (vs 6 x 7.6 = 45.6). launch_bounds(512,3) implies a 42-reg cap,
// ABOVE the current 40 -> codegen/ILP untouched (unlike R13's 32-reg squeeze).
#define SMT(warp, idx, c) smd[(((warp) * 128 + (idx)) << 2) + (c)]

__global__ __launch_bounds__(512, 3) void deform_sample6(
    const float* __restrict__ ref, const float* __restrict__ offaw,
    const __half* __restrict__ vhm, __half* __restrict__ samph)
{
    extern __shared__ uint2 smd[];   // [16][128][4] = 64KB

    const int w    = threadIdx.x >> 5;
    const int lane = threadIdx.x & 31;
    const int bq   = blockIdx.x * 16 + w;
    const int b    = bq / NQ;

    {   // ---- phase 1 ----
        const int h = lane >> 2;
        const int j = lane & 3;
        const float* aw = offaw + (size_t)bq * 384 + 256;
        float lg[4];
#pragma unroll
        for (int r = 0; r < 4; r++) lg[r] = aw[h * 16 + r * 4 + j];
        float mx = fmaxf(fmaxf(lg[0], lg[1]), fmaxf(lg[2], lg[3]));
        mx = fmaxf(mx, __shfl_xor_sync(0xffffffffu, mx, 1));
        mx = fmaxf(mx, __shfl_xor_sync(0xffffffffu, mx, 2));
        float e[4], sum = 0.f;
#pragma unroll
        for (int r = 0; r < 4; r++) { e[r] = __expf(lg[r] - mx); sum += e[r]; }
        sum += __shfl_xor_sync(0xffffffffu, sum, 1);
        sum += __shfl_xor_sync(0xffffffffu, sum, 2);
        const float inv = 1.f / sum;

        const float2* offp = (const float2*)(offaw + (size_t)bq * 384);
        const float2* refp = (const float2*)(ref + (size_t)bq * 8);
#pragma unroll
        for (int r = 0; r < 4; r++) {
            const int s = r * 4 + j;
            const int W = c_dim[r];
            const int st = c_start[r];
            const float2 o2 = offp[h * 16 + s];
            const float2 r2 = refp[r];
            const float x = fmaf(r2.x, (float)W, o2.x) - 0.5f;
            const float y = fmaf(r2.y, (float)W, o2.y) - 0.5f;
            const float xf = floorf(x), yf = floorf(y);
            const int x0 = (int)xf, y0 = (int)yf;
            const float fx = x - xf, fy = y - yf;
            const float mx0 = ((unsigned)x0 < (unsigned)W) ? 1.f : 0.f;
            const float mx1 = ((unsigned)(x0 + 1) < (unsigned)W) ? 1.f : 0.f;
            const float my0 = ((unsigned)y0 < (unsigned)W) ? 1.f : 0.f;
            const float my1 = ((unsigned)(y0 + 1) < (unsigned)W) ? 1.f : 0.f;
            const float ww = e[r] * inv;
            const float wx0 = (1.f - fx) * mx0, wx1 = fx * mx1;
            const float wy0 = (1.f - fy) * my0, wy1 = fy * my1;
            const int xc0 = min(max(x0, 0), W - 1);
            const int xc1 = min(max(x0 + 1, 0), W - 1);
            const int yc0 = min(max(y0, 0), W - 1);
            const int yc1 = min(max(y0 + 1, 0), W - 1);
            const int t00 = st + yc0 * W + xc0;
            const int t01 = st + yc0 * W + xc1;
            const int t10 = st + yc1 * W + xc0;
            const int t11 = st + yc1 * W + xc1;
            const float w00 = ww * wy0 * wx0;
            const float w01 = ww * wy0 * wx1;
            const float w10 = ww * wy1 * wx0;
            const float w11 = ww * wy1 * wx1;
            *(uint4*)&SMT(w, h * 16 + s, 0) =
                make_uint4((uint32_t)t00, __float_as_uint(w00),
                           (uint32_t)t01, __float_as_uint(w01));
            *(uint4*)&SMT(w, h * 16 + s, 2) =
                make_uint4((uint32_t)t10, __float_as_uint(w10),
                           (uint32_t)t11, __float_as_uint(w11));
        }
    }
    __syncwarp();

    // ---- phase 2 ----
    const int item_hi = lane >> 3;
    const int sub     = lane & 7;
    const int c2      = sub >> 2;
    const int chsl    = sub & 3;

#pragma unroll 1
    for (int h = 0; h < 8; h++) {
        const __half* vbh = vhm + ((size_t)(b * 8 + h)) * (NQ * 32);
        float av[8];
#pragma unroll
        for (int k = 0; k < 8; k++) av[k] = 0.f;

#pragma unroll
        for (int ldg = 0; ldg < 8; ldg++) {
            const int it  = ldg * 4 + item_hi;
            const int t   = it >> 1;
            const int i4  = (it & 1) * 2 + c2;
            const uint2 tw = SMT(w, h * 16 + t, i4);
            const int tok  = (int)tw.x;
            const float wt = __uint_as_float(tw.y);
            const uint4 raw = *(const uint4*)(vbh + (size_t)tok * 32 + chsl * 8);
            const float2 f0 = __half22float2(*(const __half2*)&raw.x);
            const float2 f1 = __half22float2(*(const __half2*)&raw.y);
            const float2 f2 = __half22float2(*(const __half2*)&raw.z);
            const float2 f3 = __half22float2(*(const __half2*)&raw.w);
            av[0] = fmaf(wt, f0.x, av[0]);
            av[1] = fmaf(wt, f0.y, av[1]);
            av[2] = fmaf(wt, f1.x, av[2]);
            av[3] = fmaf(wt, f1.y, av[3]);
            av[4] = fmaf(wt, f2.x, av[4]);
            av[5] = fmaf(wt, f2.y, av[5]);
            av[6] = fmaf(wt, f3.x, av[6]);
            av[7] = fmaf(wt, f3.y, av[7]);
        }

#pragma unroll
        for (int o = 4; o <= 16; o <<= 1)
#pragma unroll
            for (int k = 0; k < 8; k++)
                av[k] += __shfl_xor_sync(0xffffffffu, av[k], o);

        if (lane < 4) {
            __half2 h0 = __floats2half2_rn(av[0], av[1]);
            __half2 h1 = __floats2half2_rn(av[2], av[3]);
            __half2 h2 = __floats2half2_rn(av[4], av[5]);
            __half2 h3 = __floats2half2_rn(av[6], av[7]);
            uint4 u = make_uint4(*(uint32_t*)&h0, *(uint32_t*)&h1,
                                 *(uint32_t*)&h2, *(uint32_t*)&h3);
            *(uint4*)(samph + (size_t)bq * 256 + h * 32 + lane * 8) = u;
        }
    }
}

// ---------------- launch ----------------
extern "C" void kernel_launch(void* const* d_in, const int* in_sizes, int n_in,
                              void* d_out, int out_size)
{
    const float* query  = (const float*)d_in[0];
    const float* refpts = (const float*)d_in[1];
    const float* value  = (const float*)d_in[2];
    const float* W_off  = (const float*)d_in[3];
    const float* b_off  = (const float*)d_in[4];
    const float* W_attn = (const float*)d_in[5];
    const float* b_attn = (const float*)d_in[6];
    const float* W_v    = (const float*)d_in[7];
    const float* b_v    = (const float*)d_in[8];
    const float* W_out  = (const float*)d_in[9];
    const float* b_out  = (const float*)d_in[10];
    float* out = (float*)d_out;

    float *offaw_s, *bcat;
    __half *qh_s, *valh_s, *vhm_s, *samph_s, *wtcat, *wtv, *wtout;
    cudaGetSymbolAddress((void**)&qh_s,    g_qh);
    cudaGetSymbolAddress((void**)&valh_s,  g_valh);
    cudaGetSymbolAddress((void**)&offaw_s, g_offaw);
    cudaGetSymbolAddress((void**)&vhm_s,   g_vhm);
    cudaGetSymbolAddress((void**)&samph_s, g_samph);
    cudaGetSymbolAddress((void**)&wtcat,   g_wtcat);
    cudaGetSymbolAddress((void**)&wtv,     g_wtv);
    cudaGetSymbolAddress((void**)&wtout,   g_wtout);
    cudaGetSymbolAddress((void**)&bcat,    g_bcat);

    static bool attr_done = false;
    if (!attr_done) {
        cudaFuncSetAttribute(hgemm_dual,
                             cudaFuncAttributeMaxDynamicSharedMemorySize, 98304);
        cudaFuncSetAttribute(hgemm_single,
                             cudaFuncAttributeMaxDynamicSharedMemorySize, 98304);
        cudaFuncSetAttribute(deform_sample6,
                             cudaFuncAttributeMaxDynamicSharedMemorySize, 65536);
        attr_done = true;
    }

    prep_all<<<2 * F2H_BLKS + 225, 256>>>(query, value, qh_s, valh_s,
                                          W_off, W_attn, W_v, W_out,
                                          b_off, b_attn,
                                          wtcat, wtv, wtout, bcat);

    const int GM = MROWS / 128;   // 340
    hgemm_dual<<<dim3(5, GM), 256, 98304>>>(qh_s, wtcat, bcat, offaw_s,
                                            valh_s, wtv, b_v, vhm_s);

    deform_sample6<<<MROWS / 16, 512, 65536>>>(refpts, offaw_s, vhm_s, samph_s);

    hgemm_single<<<dim3(2, GM), 256, 98304>>>(samph_s, wtout, b_out, out);
}